// round 9
// baseline (speedup 1.0000x reference)
#include <cuda_runtime.h>
#include <cstdint>
#include <math.h>

#define N_TOK   8192
#define D_DIM   4096
#define E_NUM   8
#define R_RANK  128
#define SCALING 0.25f
#define MT      64

__device__ int   g_cnt[2][E_NUM];
__device__ int   g_tok[2][E_NUM][N_TOK];
__device__ float g_wt [2][E_NUM][N_TOK];
// tf32-preconverted operands (f32 bit patterns, low mantissa zeroed)
__device__ float g_xt[(size_t)N_TOK * D_DIM];            // 128 MB
__device__ float g_at[(size_t)E_NUM * R_RANK * D_DIM];   // 16 MB
__device__ float g_bt[(size_t)E_NUM * D_DIM * R_RANK];   // 16 MB

// ---- dynamic smem layout (bytes), total 101376 -> 2 CTAs/SM ----
// H: [64][132w] @ 0 (33792)
// stage1 (KB=32): X[64][36w] x2 @ 33792 (9216 ea), A[128][36w] x2 @ 52224 (18432 ea)
// stage2: B[128][132w] single @ 33792 (67584), overlays stage1
#define OFF_H    0
#define OFF_X(b) (33792 + (b) * 9216)
#define OFF_A(b) (52224 + (b) * 18432)
#define OFF_B    33792
#define SMEM_BYTES 101376

__device__ __forceinline__ uint32_t smem_u32(const void* p) {
    uint32_t a;
    asm("{ .reg .u64 t; cvta.to.shared.u64 t, %1; cvt.u32.u64 %0, t; }" : "=r"(a) : "l"(p));
    return a;
}
__device__ __forceinline__ uint32_t cvt_tf32(float f) {
    uint32_t r; asm("cvt.rna.tf32.f32 %0, %1;" : "=r"(r) : "f"(f)); return r;
}
__device__ __forceinline__ float tf32f(float f) { return __uint_as_float(cvt_tf32(f)); }

#define CP16(sa, gp) asm volatile("cp.async.cg.shared.global [%0], [%1], 16;" :: "r"(sa), "l"(gp))
#define CPCOMMIT()   asm volatile("cp.async.commit_group;" ::: "memory")
#define CPWAIT(n)    asm volatile("cp.async.wait_group %0;" :: "n"(n) : "memory")

__device__ __forceinline__ void mma8(float* c, const uint32_t* a, const uint32_t* b) {
    asm volatile("mma.sync.aligned.m16n8k8.row.col.f32.tf32.tf32.f32 "
        "{%0,%1,%2,%3}, {%4,%5,%6,%7}, {%8,%9}, {%0,%1,%2,%3};"
        : "+f"(c[0]), "+f"(c[1]), "+f"(c[2]), "+f"(c[3])
        : "r"(a[0]), "r"(a[1]), "r"(a[2]), "r"(a[3]), "r"(b[0]), "r"(b[1]));
}

// ---------------- kernels ----------------
__global__ void reset_kernel() {
    if (threadIdx.x < 2 * E_NUM) ((int*)g_cnt)[threadIdx.x] = 0;
}

__global__ __launch_bounds__(256) void cvt_wt(const float4* __restrict__ A,
                                              const float4* __restrict__ B)
{
    size_t i = (size_t)blockIdx.x * blockDim.x + threadIdx.x;
    const size_t n4 = (size_t)E_NUM * R_RANK * D_DIM / 4;
    if (i >= n4) return;
    float4 a = A[i], b = B[i];
    ((float4*)g_at)[i] = make_float4(tf32f(a.x), tf32f(a.y), tf32f(a.z), tf32f(a.w));
    ((float4*)g_bt)[i] = make_float4(tf32f(b.x), tf32f(b.y), tf32f(b.z), tf32f(b.w));
}

// Router v3: 4 tokens per block (Wr L2 traffic /4); writes tf32 copy of x.
__global__ __launch_bounds__(256) void router_kernel(
    const float* __restrict__ x, const float* __restrict__ Wr, const float* __restrict__ br)
{
    const int n0 = blockIdx.x * 4, tid = threadIdx.x;
    const int warp = tid >> 5, lane = tid & 31;

    float acc[4][E_NUM];
#pragma unroll
    for (int t = 0; t < 4; t++)
#pragma unroll
        for (int e = 0; e < E_NUM; e++) acc[t][e] = 0.f;

    for (int d = tid * 4; d < D_DIM; d += 1024) {
        float4 wv[E_NUM];
#pragma unroll
        for (int e = 0; e < E_NUM; e++) wv[e] = *(const float4*)(Wr + (size_t)e * D_DIM + d);
#pragma unroll
        for (int t = 0; t < 4; t++) {
            float4 xv = *(const float4*)(x + (size_t)(n0 + t) * D_DIM + d);
            *(float4*)(g_xt + (size_t)(n0 + t) * D_DIM + d) =
                make_float4(tf32f(xv.x), tf32f(xv.y), tf32f(xv.z), tf32f(xv.w));
#pragma unroll
            for (int e = 0; e < E_NUM; e++)
                acc[t][e] += xv.x*wv[e].x + xv.y*wv[e].y + xv.z*wv[e].z + xv.w*wv[e].w;
        }
    }
#pragma unroll
    for (int off = 16; off > 0; off >>= 1)
#pragma unroll
        for (int t = 0; t < 4; t++)
#pragma unroll
            for (int e = 0; e < E_NUM; e++)
                acc[t][e] += __shfl_xor_sync(0xffffffffu, acc[t][e], off);

    __shared__ float sm[8][4][E_NUM];
    if (lane == 0)
#pragma unroll
        for (int t = 0; t < 4; t++)
#pragma unroll
            for (int e = 0; e < E_NUM; e++) sm[warp][t][e] = acc[t][e];
    __syncthreads();
    if (tid < 4) {
        const int n = n0 + tid;
        float lg[E_NUM];
#pragma unroll
        for (int e = 0; e < E_NUM; e++) {
            float s = 0.f;
#pragma unroll
            for (int w = 0; w < 8; w++) s += sm[w][tid][e];
            lg[e] = s + br[e];
        }
        int i0 = 0;
#pragma unroll
        for (int e = 1; e < E_NUM; e++) if (lg[e] > lg[i0]) i0 = e;
        int i1 = (i0 == 0) ? 1 : 0;
#pragma unroll
        for (int e = 0; e < E_NUM; e++) if (e != i0 && lg[e] > lg[i1]) i1 = e;
        float e1  = expf(lg[i1] - lg[i0]);
        float inv = SCALING / (1.f + e1);
        int p0 = atomicAdd(&g_cnt[0][i0], 1);
        g_tok[0][i0][p0] = n;  g_wt[0][i0][p0] = inv;
        int p1 = atomicAdd(&g_cnt[1][i1], 1);
        g_tok[1][i1][p1] = n;  g_wt[1][i1][p1] = e1 * inv;
    }
}

__global__ __launch_bounds__(256, 2)
void expert_kernel(float* __restrict__ out, int slot)
{
    const int e    = blockIdx.y;
    const int cnt  = g_cnt[slot][e];
    const int base = blockIdx.x * MT;
    if (base >= cnt) return;

    extern __shared__ char dsm[];
    __shared__ int   stok[MT];
    __shared__ float swt[MT];

    const int tid  = threadIdx.x;
    const int lane = tid & 31, warp = tid >> 5;
    const int wm = warp >> 2, wn = warp & 3;     // 2m x 4n warp grid
    const int lm = lane >> 2, lk = lane & 3;

    if (tid < MT) {
        int p = base + tid;
        if (p < cnt) { stok[tid] = g_tok[slot][e][p];    swt[tid] = g_wt[slot][e][p]; }
        else         { stok[tid] = g_tok[slot][e][base]; swt[tid] = 0.f;              }
    }
    __syncthreads();

    const uint32_t sb = smem_u32(dsm);

    // ---- cp.async plumbing ----
    // X (KB=32): 64 rows, 4 thr/row: row=tid>>2, q=tid&3 -> 2 CP16 at cols q*8(+4)
    const int xr_ = tid >> 2, xq_ = tid & 3;
    const float* xg = g_xt + (size_t)stok[xr_] * D_DIM + xq_ * 8;
    const uint32_t xo = (uint32_t)xr_ * 144u + (uint32_t)xq_ * 32u;
    // A (KB=32): 128 rows, 2 thr/row: row=tid>>1, q=tid&1 -> 4 CP16 at cols q*16+j*4
    const int ar_ = tid >> 1, aq_ = tid & 1;
    const float* ag = g_at + ((size_t)e * R_RANK + ar_) * D_DIM + aq_ * 16;
    const uint32_t ao = (uint32_t)ar_ * 144u + (uint32_t)aq_ * 64u;
    // B: 128 rows, 2 thr/row: 16 CP16 at cols q*64+j*4
    const float* bg = g_bt + (size_t)e * D_DIM * R_RANK + (size_t)ar_ * R_RANK + aq_ * 64;
    const uint32_t bo = (uint32_t)ar_ * 528u + (uint32_t)aq_ * 256u;

    float c[2][4][4];
#pragma unroll
    for (int mt = 0; mt < 2; mt++)
#pragma unroll
        for (int nt = 0; nt < 4; nt++)
#pragma unroll
            for (int q = 0; q < 4; q++) c[mt][nt][q] = 0.f;

    // ============ stage 1: h = X_g @ A_e^T (K=4096, 128 tiles of 32) ============
    {
#pragma unroll
        for (int j = 0; j < 2; j++) CP16(sb + OFF_X(0) + xo + j * 16u, xg + j * 4);
#pragma unroll
        for (int j = 0; j < 4; j++) CP16(sb + OFF_A(0) + ao + j * 16u, ag + j * 4);
        CPCOMMIT();
    }
    for (int kt = 0; kt < 128; kt++) {
        if (kt + 1 < 128) {
            const int b = (kt + 1) & 1, gk = (kt + 1) * 32;
#pragma unroll
            for (int j = 0; j < 2; j++) CP16(sb + OFF_X(b) + xo + j * 16u, xg + gk + j * 4);
#pragma unroll
            for (int j = 0; j < 4; j++) CP16(sb + OFF_A(b) + ao + j * 16u, ag + gk + j * 4);
            CPCOMMIT();
            CPWAIT(1);
        } else {
            CPWAIT(0);
        }
        __syncthreads();
        const uint32_t* Xs = (const uint32_t*)(dsm + OFF_X(kt & 1));
        const uint32_t* As = (const uint32_t*)(dsm + OFF_A(kt & 1));
#pragma unroll
        for (int ks = 0; ks < 4; ks++) {
            const int k0 = ks * 8 + lk;
            uint32_t af[2][4], bf[4][2];
#pragma unroll
            for (int mt = 0; mt < 2; mt++) {
                const int r0 = wm * 32 + mt * 16 + lm;
                af[mt][0] = Xs[r0 * 36 + k0];
                af[mt][1] = Xs[(r0 + 8) * 36 + k0];
                af[mt][2] = Xs[r0 * 36 + k0 + 4];
                af[mt][3] = Xs[(r0 + 8) * 36 + k0 + 4];
            }
#pragma unroll
            for (int nt = 0; nt < 4; nt++) {
                const int n0 = wn * 32 + nt * 8 + lm;
                bf[nt][0] = As[n0 * 36 + k0];
                bf[nt][1] = As[n0 * 36 + k0 + 4];
            }
#pragma unroll
            for (int mt = 0; mt < 2; mt++)
#pragma unroll
                for (int nt = 0; nt < 4; nt++) mma8(c[mt][nt], af[mt], bf[nt]);
        }
        __syncthreads();
    }

    // ---- H epilogue: gate-weight + tf32 -> smem (stride 132) ----
    uint32_t* Hs = (uint32_t*)(dsm + OFF_H);
    int   tk[2][2]; float ww[2][2]; bool vv[2][2];
#pragma unroll
    for (int mt = 0; mt < 2; mt++)
#pragma unroll
        for (int h = 0; h < 2; h++) {
            const int r = wm * 32 + mt * 16 + lm + h * 8;
            tk[mt][h] = stok[r]; ww[mt][h] = swt[r]; vv[mt][h] = (base + r) < cnt;
        }
    // stage-2 chunk0 load overlaps the H writes (B region = dead stage-1 buffers)
#pragma unroll
    for (int j = 0; j < 16; j++)
        CP16(sb + OFF_B + bo + j * 16u, bg + j * 4);
    CPCOMMIT();
#pragma unroll
    for (int mt = 0; mt < 2; mt++)
#pragma unroll
        for (int h = 0; h < 2; h++) {
            const int r = wm * 32 + mt * 16 + lm + h * 8;
#pragma unroll
            for (int nt = 0; nt < 4; nt++) {
                const int col = wn * 32 + nt * 8 + lk * 2;
                uint2 v;
                v.x = cvt_tf32(c[mt][nt][h * 2]     * ww[mt][h]);
                v.y = cvt_tf32(c[mt][nt][h * 2 + 1] * ww[mt][h]);
                *(uint2*)&Hs[r * 132 + col] = v;
            }
        }

    // ============ stage 2: out (+)= H @ B_e^T (32 chunks, single buffer) ======
    for (int ch = 0; ch < 32; ch++) {
        CPWAIT(0);
        __syncthreads();
#pragma unroll
        for (int mt = 0; mt < 2; mt++)
#pragma unroll
            for (int nt = 0; nt < 4; nt++)
#pragma unroll
                for (int q = 0; q < 4; q++) c[mt][nt][q] = 0.f;

        const uint32_t* Bs = (const uint32_t*)(dsm + OFF_B);
#pragma unroll
        for (int ks = 0; ks < 16; ks++) {
            const int k0 = ks * 8 + lk;
            uint32_t af[2][4], bf[4][2];
#pragma unroll
            for (int mt = 0; mt < 2; mt++) {
                const int r0 = wm * 32 + mt * 16 + lm;
                af[mt][0] = Hs[r0 * 132 + k0];
                af[mt][1] = Hs[(r0 + 8) * 132 + k0];
                af[mt][2] = Hs[r0 * 132 + k0 + 4];
                af[mt][3] = Hs[(r0 + 8) * 132 + k0 + 4];
            }
#pragma unroll
            for (int nt = 0; nt < 4; nt++) {
                const int n0 = wn * 32 + nt * 8 + lm;
                bf[nt][0] = Bs[n0 * 132 + k0];
                bf[nt][1] = Bs[n0 * 132 + k0 + 4];
            }
#pragma unroll
            for (int mt = 0; mt < 2; mt++)
#pragma unroll
                for (int nt = 0; nt < 4; nt++) mma8(c[mt][nt], af[mt], bf[nt]);
        }
        __syncthreads();   // everyone done reading B before overwrite
        if (ch + 1 < 32) { // next-chunk load overlaps the out-store epilogue below
            const float* gp = bg + (size_t)(ch + 1) * 128 * R_RANK;
#pragma unroll
            for (int j = 0; j < 16; j++)
                CP16(sb + OFF_B + bo + j * 16u, gp + j * 4);
            CPCOMMIT();
        }
        const int d0 = ch * 128;
#pragma unroll
        for (int mt = 0; mt < 2; mt++)
#pragma unroll
            for (int h = 0; h < 2; h++) {
                if (!vv[mt][h]) continue;
                float* op = out + (size_t)tk[mt][h] * D_DIM + d0 + wn * 32 + lk * 2;
                if (slot == 0) {
#pragma unroll
                    for (int nt = 0; nt < 4; nt++)
                        *(float2*)(op + nt * 8) =
                            make_float2(c[mt][nt][h * 2], c[mt][nt][h * 2 + 1]);
                } else {
#pragma unroll
                    for (int nt = 0; nt < 4; nt++) {
                        float2 o = *(const float2*)(op + nt * 8);
                        o.x += c[mt][nt][h * 2];
                        o.y += c[mt][nt][h * 2 + 1];
                        *(float2*)(op + nt * 8) = o;
                    }
                }
            }
    }
}

extern "C" void kernel_launch(void* const* d_in, const int* in_sizes, int n_in,
                              void* d_out, int out_size)
{
    (void)in_sizes; (void)n_in; (void)out_size;
    const float* x  = (const float*)d_in[0];
    const float* Wr = (const float*)d_in[1];
    const float* br = (const float*)d_in[2];
    const float* A  = (const float*)d_in[3];
    const float* B  = (const float*)d_in[4];
    float* out = (float*)d_out;

    cudaFuncSetAttribute(expert_kernel, cudaFuncAttributeMaxDynamicSharedMemorySize, SMEM_BYTES);
    reset_kernel<<<1, 32>>>();
    cvt_wt<<<(E_NUM * R_RANK * D_DIM / 4 + 255) / 256, 256>>>((const float4*)A, (const float4*)B);
    router_kernel<<<N_TOK / 4, 256>>>(x, Wr, br);
    dim3 grid(N_TOK / MT, E_NUM);
    expert_kernel<<<grid, 256, SMEM_BYTES>>>(out, 0);
    expert_kernel<<<grid, 256, SMEM_BYTES>>>(out, 1);
}

// round 10
// speedup vs baseline: 1.8094x; 1.8094x over previous
#include <cuda_runtime.h>
#include <cstdint>
#include <math.h>

#define N_TOK   8192
#define D_DIM   4096
#define E_NUM   8
#define R_RANK  128
#define SCALING 0.25f
#define MT      64

__device__ int   g_cnt[2][E_NUM];
__device__ int   g_tok[2][E_NUM][N_TOK];
__device__ float g_wt [2][E_NUM][N_TOK];
// tf32-preconverted weights (f32 bit patterns, low mantissa zeroed)
__device__ float g_at[(size_t)E_NUM * R_RANK * D_DIM];   // 16 MB
__device__ float g_bt[(size_t)E_NUM * D_DIM * R_RANK];   // 16 MB

// ---- dynamic smem layout (bytes) ----
// H: [64][132w] @ 0 (33792)
// stage1 (KB=64): X[64][68w] x2 @ 33792 (17408 ea), A[128][68w] x2 @ 68608 (34816 ea)
// stage2: B[128][132w] x2 @ 33792 (67584 ea), overlays stage1
#define OFF_H    0
#define OFF_X(b) (33792 + (b) * 17408)
#define OFF_A(b) (68608 + (b) * 34816)
#define OFF_B(b) (33792 + (b) * 67584)
#define SMEM_BYTES 168960

__device__ __forceinline__ uint32_t smem_u32(const void* p) {
    uint32_t a;
    asm("{ .reg .u64 t; cvta.to.shared.u64 t, %1; cvt.u32.u64 %0, t; }" : "=r"(a) : "l"(p));
    return a;
}
__device__ __forceinline__ uint32_t cvt_tf32(float f) {
    uint32_t r; asm("cvt.rna.tf32.f32 %0, %1;" : "=r"(r) : "f"(f)); return r;
}
__device__ __forceinline__ float tf32f(float f) { return __uint_as_float(cvt_tf32(f)); }

#define CP16(sa, gp) asm volatile("cp.async.cg.shared.global [%0], [%1], 16;" :: "r"(sa), "l"(gp))
#define CPCOMMIT()   asm volatile("cp.async.commit_group;" ::: "memory")
#define CPWAIT(n)    asm volatile("cp.async.wait_group %0;" :: "n"(n) : "memory")

__device__ __forceinline__ void mma8(float* c, const uint32_t* a, const uint32_t* b) {
    asm volatile("mma.sync.aligned.m16n8k8.row.col.f32.tf32.tf32.f32 "
        "{%0,%1,%2,%3}, {%4,%5,%6,%7}, {%8,%9}, {%0,%1,%2,%3};"
        : "+f"(c[0]), "+f"(c[1]), "+f"(c[2]), "+f"(c[3])
        : "r"(a[0]), "r"(a[1]), "r"(a[2]), "r"(a[3]), "r"(b[0]), "r"(b[1]));
}

// ---------------- kernels ----------------
__global__ void reset_kernel() {
    if (threadIdx.x < 2 * E_NUM) ((int*)g_cnt)[threadIdx.x] = 0;
}

__global__ __launch_bounds__(256) void cvt_wt(const float4* __restrict__ A,
                                              const float4* __restrict__ B)
{
    size_t i = (size_t)blockIdx.x * blockDim.x + threadIdx.x;
    const size_t n4 = (size_t)E_NUM * R_RANK * D_DIM / 4;
    if (i >= n4) return;
    float4 a = A[i], b = B[i];
    ((float4*)g_at)[i] = make_float4(tf32f(a.x), tf32f(a.y), tf32f(a.z), tf32f(a.w));
    ((float4*)g_bt)[i] = make_float4(tf32f(b.x), tf32f(b.y), tf32f(b.z), tf32f(b.w));
}

// Router (R4-proven, part of the 514us total): 1 block/token, no side writes.
__global__ __launch_bounds__(256) void router_kernel(
    const float* __restrict__ x, const float* __restrict__ Wr, const float* __restrict__ br)
{
    const int n = blockIdx.x, tid = threadIdx.x;
    const float* xr = x + (size_t)n * D_DIM;
    float acc[E_NUM];
#pragma unroll
    for (int e = 0; e < E_NUM; e++) acc[e] = 0.f;
    for (int d = tid * 4; d < D_DIM; d += 1024) {
        float4 xv = *(const float4*)(xr + d);
#pragma unroll
        for (int e = 0; e < E_NUM; e++) {
            float4 wv = *(const float4*)(Wr + (size_t)e * D_DIM + d);
            acc[e] += xv.x*wv.x + xv.y*wv.y + xv.z*wv.z + xv.w*wv.w;
        }
    }
#pragma unroll
    for (int e = 0; e < E_NUM; e++)
#pragma unroll
        for (int off = 16; off > 0; off >>= 1)
            acc[e] += __shfl_xor_sync(0xffffffffu, acc[e], off);
    __shared__ float sm[E_NUM][8];
    const int warp = tid >> 5, lane = tid & 31;
    if (lane == 0)
#pragma unroll
        for (int e = 0; e < E_NUM; e++) sm[e][warp] = acc[e];
    __syncthreads();
    if (tid == 0) {
        float lg[E_NUM];
#pragma unroll
        for (int e = 0; e < E_NUM; e++) {
            float s = 0.f;
#pragma unroll
            for (int w = 0; w < 8; w++) s += sm[e][w];
            lg[e] = s + br[e];
        }
        int i0 = 0;
#pragma unroll
        for (int e = 1; e < E_NUM; e++) if (lg[e] > lg[i0]) i0 = e;
        int i1 = (i0 == 0) ? 1 : 0;
#pragma unroll
        for (int e = 0; e < E_NUM; e++) if (e != i0 && lg[e] > lg[i1]) i1 = e;
        float e1  = expf(lg[i1] - lg[i0]);
        float inv = SCALING / (1.f + e1);
        int p0 = atomicAdd(&g_cnt[0][i0], 1);
        g_tok[0][i0][p0] = n;  g_wt[0][i0][p0] = inv;
        int p1 = atomicAdd(&g_cnt[1][i1], 1);
        g_tok[1][i1][p1] = n;  g_wt[1][i1][p1] = e1 * inv;
    }
}

__global__ __launch_bounds__(256, 1)
void expert_kernel(const float* __restrict__ x, float* __restrict__ out, int slot)
{
    const int e    = blockIdx.y;
    const int cnt  = g_cnt[slot][e];
    const int base = blockIdx.x * MT;
    if (base >= cnt) return;

    extern __shared__ char dsm[];
    __shared__ int   stok[MT];
    __shared__ float swt[MT];

    const int tid  = threadIdx.x;
    const int lane = tid & 31, warp = tid >> 5;
    const int wm = warp >> 2, wn = warp & 3;     // warp grid 2m x 4n
    const int lm = lane >> 2, lk = lane & 3;

    if (tid < MT) {
        int p = base + tid;
        if (p < cnt) { stok[tid] = g_tok[slot][e][p];    swt[tid] = g_wt[slot][e][p]; }
        else         { stok[tid] = g_tok[slot][e][base]; swt[tid] = 0.f;              }
    }
    __syncthreads();

    const uint32_t sb = smem_u32(dsm);

    // ---- X loader: raw x, LDG -> cvt -> STS.128; row = tid&63 (conflict-free) ----
    const int xr_ = tid & 63, xq_ = tid >> 6;    // row, col16-group
    const float* xg = x + (size_t)stok[xr_] * D_DIM + xq_ * 16;
    const uint32_t xw = (uint32_t)xr_ * 68u + (uint32_t)xq_ * 16u;   // word offset
    float xf[16];

    // ---- A loader: cp.async from g_at (preconverted) ----
    const int ar_ = tid >> 1, aq_ = tid & 1;
    const float* ag = g_at + ((size_t)e * R_RANK + ar_) * D_DIM + aq_ * 32;
    const uint32_t ao = (uint32_t)ar_ * 272u + (uint32_t)aq_ * 128u; // bytes
    // ---- B loader: cp.async from g_bt ----
    const float* bg = g_bt + (size_t)e * D_DIM * R_RANK + (size_t)warp * R_RANK + lane * 4;
    const uint32_t bo = (uint32_t)warp * 528u + (uint32_t)lane * 16u;

    float c[2][4][4];
#pragma unroll
    for (int mt = 0; mt < 2; mt++)
#pragma unroll
        for (int nt = 0; nt < 4; nt++)
#pragma unroll
            for (int q = 0; q < 4; q++) c[mt][nt][q] = 0.f;

#define LOADX(KT) do {                                                        \
    const int _g = (KT) * 64;                                                 \
    _Pragma("unroll")                                                         \
    for (int _i = 0; _i < 4; _i++)                                            \
        *(float4*)&xf[_i * 4] = *(const float4*)(xg + _g + _i * 4);           \
} while (0)

    // ============ stage 1: h = X_g @ A_e^T (K=4096, 64 tiles of 64) ============
    LOADX(0);
#pragma unroll
    for (int j = 0; j < 8; j++) CP16(sb + OFF_A(0) + ao + j * 16u, ag + j * 4);
    CPCOMMIT();

    for (int kt = 0; kt < 64; kt++) {
        // STS X tile kt (tf32 rounding happens here; once per element)
        {
            uint32_t* Xw = (uint32_t*)(dsm + OFF_X(kt & 1)) + xw;
#pragma unroll
            for (int j = 0; j < 4; j++)
                *(uint4*)&Xw[j * 4] = make_uint4(cvt_tf32(xf[j*4]),   cvt_tf32(xf[j*4+1]),
                                                 cvt_tf32(xf[j*4+2]), cvt_tf32(xf[j*4+3]));
        }
        if (kt + 1 < 64) {
            const int b = (kt + 1) & 1, gk = (kt + 1) * 64;
#pragma unroll
            for (int j = 0; j < 8; j++) CP16(sb + OFF_A(b) + ao + j * 16u, ag + gk + j * 4);
            CPCOMMIT();
            CPWAIT(1);          // A[kt] resident
        } else {
            CPWAIT(0);
        }
        __syncthreads();
        if (kt + 1 < 64) LOADX(kt + 1);   // LDG next X overlaps the mma loop

        const uint32_t* Xs = (const uint32_t*)(dsm + OFF_X(kt & 1));
        const uint32_t* As = (const uint32_t*)(dsm + OFF_A(kt & 1));
#pragma unroll
        for (int ks = 0; ks < 8; ks++) {
            const int k0 = ks * 8 + lk;
            uint32_t af[2][4], bf[4][2];
#pragma unroll
            for (int mt = 0; mt < 2; mt++) {
                const int r0 = wm * 32 + mt * 16 + lm;
                af[mt][0] = Xs[r0 * 68 + k0];
                af[mt][1] = Xs[(r0 + 8) * 68 + k0];
                af[mt][2] = Xs[r0 * 68 + k0 + 4];
                af[mt][3] = Xs[(r0 + 8) * 68 + k0 + 4];
            }
#pragma unroll
            for (int nt = 0; nt < 4; nt++) {
                const int n0 = wn * 32 + nt * 8 + lm;
                bf[nt][0] = As[n0 * 68 + k0];
                bf[nt][1] = As[n0 * 68 + k0 + 4];
            }
#pragma unroll
            for (int mt = 0; mt < 2; mt++)
#pragma unroll
                for (int nt = 0; nt < 4; nt++) mma8(c[mt][nt], af[mt], bf[nt]);
        }
        __syncthreads();
    }

    // ---- stage2 chunk0 prefetch (stage-1 buffers now dead) ----
#pragma unroll
    for (int j = 0; j < 16; j++)
        CP16(sb + OFF_B(0) + bo + j * 4224u, bg + (size_t)j * 8 * R_RANK);
    CPCOMMIT();

    // ---- H epilogue: gate-weight + tf32 -> smem (stride 132) ----
    uint32_t* Hs = (uint32_t*)(dsm + OFF_H);
    int   tk[2][2]; float ww[2][2]; bool vv[2][2];
#pragma unroll
    for (int mt = 0; mt < 2; mt++)
#pragma unroll
        for (int h = 0; h < 2; h++) {
            const int r = wm * 32 + mt * 16 + lm + h * 8;
            tk[mt][h] = stok[r]; ww[mt][h] = swt[r]; vv[mt][h] = (base + r) < cnt;
        }
#pragma unroll
    for (int mt = 0; mt < 2; mt++)
#pragma unroll
        for (int h = 0; h < 2; h++) {
            const int r = wm * 32 + mt * 16 + lm + h * 8;
#pragma unroll
            for (int nt = 0; nt < 4; nt++) {
                const int col = wn * 32 + nt * 8 + lk * 2;
                uint2 v;
                v.x = cvt_tf32(c[mt][nt][h * 2]     * ww[mt][h]);
                v.y = cvt_tf32(c[mt][nt][h * 2 + 1] * ww[mt][h]);
                *(uint2*)&Hs[r * 132 + col] = v;
            }
        }
    __syncthreads();

    // ============ stage 2: out (+)= H @ B_e^T (32 chunks of N=128) ============
    for (int ch = 0; ch < 32; ch++) {
        if (ch + 1 < 32) {
            const int b = (ch + 1) & 1;
            const float* gp = bg + (size_t)(ch + 1) * 128 * R_RANK;
#pragma unroll
            for (int j = 0; j < 16; j++)
                CP16(sb + OFF_B(b) + bo + j * 4224u, gp + (size_t)j * 8 * R_RANK);
            CPCOMMIT();
            CPWAIT(1);
        } else {
            CPWAIT(0);
        }
        __syncthreads();
#pragma unroll
        for (int mt = 0; mt < 2; mt++)
#pragma unroll
            for (int nt = 0; nt < 4; nt++)
#pragma unroll
                for (int q = 0; q < 4; q++) c[mt][nt][q] = 0.f;

        const uint32_t* Bs = (const uint32_t*)(dsm + OFF_B(ch & 1));
#pragma unroll
        for (int ks = 0; ks < 16; ks++) {
            const int k0 = ks * 8 + lk;
            uint32_t af[2][4], bf[4][2];
#pragma unroll
            for (int mt = 0; mt < 2; mt++) {
                const int r0 = wm * 32 + mt * 16 + lm;
                af[mt][0] = Hs[r0 * 132 + k0];
                af[mt][1] = Hs[(r0 + 8) * 132 + k0];
                af[mt][2] = Hs[r0 * 132 + k0 + 4];
                af[mt][3] = Hs[(r0 + 8) * 132 + k0 + 4];
            }
#pragma unroll
            for (int nt = 0; nt < 4; nt++) {
                const int n0 = wn * 32 + nt * 8 + lm;
                bf[nt][0] = Bs[n0 * 132 + k0];
                bf[nt][1] = Bs[n0 * 132 + k0 + 4];
            }
#pragma unroll
            for (int mt = 0; mt < 2; mt++)
#pragma unroll
                for (int nt = 0; nt < 4; nt++) mma8(c[mt][nt], af[mt], bf[nt]);
        }
        const int d0 = ch * 128;
#pragma unroll
        for (int mt = 0; mt < 2; mt++)
#pragma unroll
            for (int h = 0; h < 2; h++) {
                if (!vv[mt][h]) continue;
                float* op = out + (size_t)tk[mt][h] * D_DIM + d0 + wn * 32 + lk * 2;
                if (slot == 0) {
#pragma unroll
                    for (int nt = 0; nt < 4; nt++)
                        *(float2*)(op + nt * 8) =
                            make_float2(c[mt][nt][h * 2], c[mt][nt][h * 2 + 1]);
                } else {
#pragma unroll
                    for (int nt = 0; nt < 4; nt++) {
                        float2 o = *(const float2*)(op + nt * 8);
                        o.x += c[mt][nt][h * 2];
                        o.y += c[mt][nt][h * 2 + 1];
                        *(float2*)(op + nt * 8) = o;
                    }
                }
            }
        __syncthreads();
    }
}

extern "C" void kernel_launch(void* const* d_in, const int* in_sizes, int n_in,
                              void* d_out, int out_size)
{
    (void)in_sizes; (void)n_in; (void)out_size;
    const float* x  = (const float*)d_in[0];
    const float* Wr = (const float*)d_in[1];
    const float* br = (const float*)d_in[2];
    const float* A  = (const float*)d_in[3];
    const float* B  = (const float*)d_in[4];
    float* out = (float*)d_out;

    cudaFuncSetAttribute(expert_kernel, cudaFuncAttributeMaxDynamicSharedMemorySize, SMEM_BYTES);
    reset_kernel<<<1, 32>>>();
    cvt_wt<<<(E_NUM * R_RANK * D_DIM / 4 + 255) / 256, 256>>>((const float4*)A, (const float4*)B);
    router_kernel<<<N_TOK, 256>>>(x, Wr, br);
    dim3 grid(N_TOK / MT, E_NUM);
    expert_kernel<<<grid, 256, SMEM_BYTES>>>(x, out, 0);
    expert_kernel<<<grid, 256, SMEM_BYTES>>>(x, out, 1);
}

// round 11
// speedup vs baseline: 2.1176x; 1.1703x over previous
#include <cuda_runtime.h>
#include <cstdint>
#include <math.h>

#define N_TOK   8192
#define D_DIM   4096
#define E_NUM   8
#define R_RANK  128
#define SCALING 0.25f
#define MT      64

__device__ int   g_cnt[2][E_NUM];
__device__ int   g_tok[2][E_NUM][N_TOK];
__device__ float g_wt [2][E_NUM][N_TOK];

// ---- dynamic smem layout (bytes) ----
#define SZ_H        (64 * 132 * 4)                 // 33792: H tile [64][132w] tf32
#define OFF_S1X(b)  (SZ_H + (b) * 9216)            // X tile [64][36w]  x2
#define OFF_S1A(b)  (SZ_H + 18432 + (b) * 18432)   // A tile [128][36w] x2
#define OFF_S2B(b)  (SZ_H + (b) * 67584)           // B chunk [128][132w] x2 (reuses S1)
#define SMEM_BYTES  (SZ_H + 2 * 67584)             // 168960

__device__ __forceinline__ uint32_t smem_u32(const void* p) {
    uint32_t a;
    asm("{ .reg .u64 t; cvta.to.shared.u64 t, %1; cvt.u32.u64 %0, t; }" : "=r"(a) : "l"(p));
    return a;
}
__device__ __forceinline__ uint32_t cvt_tf32(float f) {
    uint32_t r; asm("cvt.rna.tf32.f32 %0, %1;" : "=r"(r) : "f"(f)); return r;
}

#define CP16(sa, gp) asm volatile("cp.async.cg.shared.global [%0], [%1], 16;" :: "r"(sa), "l"(gp))
#define CPCOMMIT()   asm volatile("cp.async.commit_group;" ::: "memory")
#define CPWAIT(n)    asm volatile("cp.async.wait_group %0;" :: "n"(n) : "memory")

__device__ __forceinline__ void mma8(float* c, const uint32_t* a, const uint32_t* b) {
    asm volatile("mma.sync.aligned.m16n8k8.row.col.f32.tf32.tf32.f32 "
        "{%0,%1,%2,%3}, {%4,%5,%6,%7}, {%8,%9}, {%0,%1,%2,%3};"
        : "+f"(c[0]), "+f"(c[1]), "+f"(c[2]), "+f"(c[3])
        : "r"(a[0]), "r"(a[1]), "r"(a[2]), "r"(a[3]), "r"(b[0]), "r"(b[1]));
}

// ---------------- kernels ----------------
__global__ void reset_kernel() {
    if (threadIdx.x < 2 * E_NUM) ((int*)g_cnt)[threadIdx.x] = 0;
}

// Router v4: 4 tokens per block -> Wr L2 traffic /4 vs 1-token blocks.
// No scratch writes. Same logits math as before (top-2 renorm from logits).
__global__ __launch_bounds__(256) void router_kernel(
    const float* __restrict__ x, const float* __restrict__ Wr, const float* __restrict__ br)
{
    const int n0 = blockIdx.x * 4, tid = threadIdx.x;
    const int warp = tid >> 5, lane = tid & 31;

    float acc[4][E_NUM];
#pragma unroll
    for (int t = 0; t < 4; t++)
#pragma unroll
        for (int e = 0; e < E_NUM; e++) acc[t][e] = 0.f;

    for (int d = tid * 4; d < D_DIM; d += 1024) {
        float4 wv[E_NUM];
#pragma unroll
        for (int e = 0; e < E_NUM; e++) wv[e] = *(const float4*)(Wr + (size_t)e * D_DIM + d);
#pragma unroll
        for (int t = 0; t < 4; t++) {
            float4 xv = *(const float4*)(x + (size_t)(n0 + t) * D_DIM + d);
#pragma unroll
            for (int e = 0; e < E_NUM; e++)
                acc[t][e] += xv.x*wv[e].x + xv.y*wv[e].y + xv.z*wv[e].z + xv.w*wv[e].w;
        }
    }
#pragma unroll
    for (int off = 16; off > 0; off >>= 1)
#pragma unroll
        for (int t = 0; t < 4; t++)
#pragma unroll
            for (int e = 0; e < E_NUM; e++)
                acc[t][e] += __shfl_xor_sync(0xffffffffu, acc[t][e], off);

    __shared__ float sm[8][4][E_NUM];
    if (lane == 0)
#pragma unroll
        for (int t = 0; t < 4; t++)
#pragma unroll
            for (int e = 0; e < E_NUM; e++) sm[warp][t][e] = acc[t][e];
    __syncthreads();
    if (tid < 4) {
        const int n = n0 + tid;
        float lg[E_NUM];
#pragma unroll
        for (int e = 0; e < E_NUM; e++) {
            float s = 0.f;
#pragma unroll
            for (int w = 0; w < 8; w++) s += sm[w][tid][e];
            lg[e] = s + br[e];
        }
        int i0 = 0;
#pragma unroll
        for (int e = 1; e < E_NUM; e++) if (lg[e] > lg[i0]) i0 = e;
        int i1 = (i0 == 0) ? 1 : 0;
#pragma unroll
        for (int e = 0; e < E_NUM; e++) if (e != i0 && lg[e] > lg[i1]) i1 = e;
        float e1  = expf(lg[i1] - lg[i0]);
        float inv = SCALING / (1.f + e1);
        int p0 = atomicAdd(&g_cnt[0][i0], 1);
        g_tok[0][i0][p0] = n;  g_wt[0][i0][p0] = inv;
        int p1 = atomicAdd(&g_cnt[1][i1], 1);
        g_tok[1][i1][p1] = n;  g_wt[1][i1][p1] = e1 * inv;
    }
}

// Expert kernel: EXACT R4 engine (best replay total measured).
__global__ __launch_bounds__(256, 1)
void expert_kernel(const float* __restrict__ x, const float* __restrict__ A,
                   const float* __restrict__ B, float* __restrict__ out, int slot)
{
    const int e    = blockIdx.y;
    const int cnt  = g_cnt[slot][e];
    const int base = blockIdx.x * MT;
    if (base >= cnt) return;

    extern __shared__ char dsm[];
    __shared__ int   stok[MT];
    __shared__ float swt[MT];

    const int tid  = threadIdx.x;
    const int lane = tid & 31, warp = tid >> 5;
    const int wm = warp >> 2, wn = warp & 3;     // warp grid 2m x 4n
    const int lm = lane >> 2, lk = lane & 3;

    if (tid < MT) {
        int p = base + tid;
        if (p < cnt) { stok[tid] = g_tok[slot][e][p];    swt[tid] = g_wt[slot][e][p]; }
        else         { stok[tid] = g_tok[slot][e][base]; swt[tid] = 0.f;              }
    }
    __syncthreads();

    const uint32_t sb = smem_u32(dsm);

    // ---- cp.async plumbing ----
    const int xr0 = tid >> 3, xc = tid & 7;
    const float* xg0 = x + (size_t)stok[xr0]      * D_DIM + xc * 4;
    const float* xg1 = x + (size_t)stok[xr0 + 32] * D_DIM + xc * 4;
    const uint32_t xo0 = (uint32_t)xr0 * 144u + (uint32_t)xc * 16u;
    const uint32_t xo1 = (uint32_t)(xr0 + 32) * 144u + (uint32_t)xc * 16u;
    const float* ag0 = A + ((size_t)e * R_RANK + xr0) * D_DIM + xc * 4;
    const uint32_t ao0 = (uint32_t)xr0 * 144u + (uint32_t)xc * 16u;
    const float* bg0 = B + (size_t)e * D_DIM * R_RANK + (size_t)warp * R_RANK + lane * 4;
    const uint32_t bo0 = (uint32_t)warp * 528u + (uint32_t)lane * 16u;

    float c[2][4][4];
#pragma unroll
    for (int mt = 0; mt < 2; mt++)
#pragma unroll
        for (int nt = 0; nt < 4; nt++)
#pragma unroll
            for (int q = 0; q < 4; q++) c[mt][nt][q] = 0.f;

    // ================= stage 1: h = X_g @ A_e^T =================
    {
        CP16(sb + OFF_S1X(0) + xo0, xg0);
        CP16(sb + OFF_S1X(0) + xo1, xg1);
#pragma unroll
        for (int j = 0; j < 4; j++)
            CP16(sb + OFF_S1A(0) + ao0 + j * 4608u, ag0 + (size_t)j * 32 * D_DIM);
        CPCOMMIT();
    }
    for (int kt = 0; kt < 128; kt++) {
        if (kt + 1 < 128) {
            const int b = (kt + 1) & 1, gk = (kt + 1) * 32;
            CP16(sb + OFF_S1X(b) + xo0, xg0 + gk);
            CP16(sb + OFF_S1X(b) + xo1, xg1 + gk);
#pragma unroll
            for (int j = 0; j < 4; j++)
                CP16(sb + OFF_S1A(b) + ao0 + j * 4608u, ag0 + (size_t)j * 32 * D_DIM + gk);
            CPCOMMIT();
            CPWAIT(1);
        } else {
            CPWAIT(0);
        }
        __syncthreads();
        const float* Xs = (const float*)(dsm + OFF_S1X(kt & 1));
        const float* As = (const float*)(dsm + OFF_S1A(kt & 1));
#pragma unroll
        for (int ks = 0; ks < 4; ks++) {
            const int k0 = ks * 8 + lk;
            uint32_t af[2][4], bf[4][2];
#pragma unroll
            for (int mt = 0; mt < 2; mt++) {
                const int r0 = wm * 32 + mt * 16 + lm;
                af[mt][0] = cvt_tf32(Xs[r0 * 36 + k0]);
                af[mt][1] = cvt_tf32(Xs[(r0 + 8) * 36 + k0]);
                af[mt][2] = cvt_tf32(Xs[r0 * 36 + k0 + 4]);
                af[mt][3] = cvt_tf32(Xs[(r0 + 8) * 36 + k0 + 4]);
            }
#pragma unroll
            for (int nt = 0; nt < 4; nt++) {
                const int n0 = wn * 32 + nt * 8 + lm;
                bf[nt][0] = cvt_tf32(As[n0 * 36 + k0]);
                bf[nt][1] = cvt_tf32(As[n0 * 36 + k0 + 4]);
            }
#pragma unroll
            for (int mt = 0; mt < 2; mt++)
#pragma unroll
                for (int nt = 0; nt < 4; nt++) mma8(c[mt][nt], af[mt], bf[nt]);
        }
        __syncthreads();
    }

    // ---- stage2 chunk0 prefetch (S1 buffers now dead) ----
    {
        CPWAIT(0);
#pragma unroll
        for (int j = 0; j < 16; j++)
            CP16(sb + OFF_S2B(0) + bo0 + j * 4224u, bg0 + (size_t)j * 8 * R_RANK);
        CPCOMMIT();
    }

    // ---- H epilogue: gate-weight + tf32 -> smem ----
    uint32_t* Hs = (uint32_t*)dsm;
    int   tk[2][2]; float ww[2][2]; bool vv[2][2];
#pragma unroll
    for (int mt = 0; mt < 2; mt++)
#pragma unroll
        for (int h = 0; h < 2; h++) {
            const int r = wm * 32 + mt * 16 + lm + h * 8;
            tk[mt][h] = stok[r]; ww[mt][h] = swt[r]; vv[mt][h] = (base + r) < cnt;
        }
#pragma unroll
    for (int mt = 0; mt < 2; mt++)
#pragma unroll
        for (int h = 0; h < 2; h++) {
            const int r = wm * 32 + mt * 16 + lm + h * 8;
#pragma unroll
            for (int nt = 0; nt < 4; nt++) {
                const int col = wn * 32 + nt * 8 + lk * 2;
                uint2 v;
                v.x = cvt_tf32(c[mt][nt][h * 2]     * ww[mt][h]);
                v.y = cvt_tf32(c[mt][nt][h * 2 + 1] * ww[mt][h]);
                *(uint2*)&Hs[r * 132 + col] = v;
            }
        }
    __syncthreads();

    // ================= stage 2: out (+)= H @ B_e^T =================
    for (int ch = 0; ch < 32; ch++) {
        if (ch + 1 < 32) {
            const int b = (ch + 1) & 1;
            const float* gp = bg0 + (size_t)(ch + 1) * 128 * R_RANK;
#pragma unroll
            for (int j = 0; j < 16; j++)
                CP16(sb + OFF_S2B(b) + bo0 + j * 4224u, gp + (size_t)j * 8 * R_RANK);
            CPCOMMIT();
            CPWAIT(1);
        } else {
            CPWAIT(0);
        }
        __syncthreads();
#pragma unroll
        for (int mt = 0; mt < 2; mt++)
#pragma unroll
            for (int nt = 0; nt < 4; nt++)
#pragma unroll
                for (int q = 0; q < 4; q++) c[mt][nt][q] = 0.f;

        const float* Bs = (const float*)(dsm + OFF_S2B(ch & 1));
#pragma unroll
        for (int ks = 0; ks < 16; ks++) {
            const int k0 = ks * 8 + lk;
            uint32_t af[2][4], bf[4][2];
#pragma unroll
            for (int mt = 0; mt < 2; mt++) {
                const int r0 = wm * 32 + mt * 16 + lm;
                af[mt][0] = Hs[r0 * 132 + k0];
                af[mt][1] = Hs[(r0 + 8) * 132 + k0];
                af[mt][2] = Hs[r0 * 132 + k0 + 4];
                af[mt][3] = Hs[(r0 + 8) * 132 + k0 + 4];
            }
#pragma unroll
            for (int nt = 0; nt < 4; nt++) {
                const int n0 = wn * 32 + nt * 8 + lm;
                bf[nt][0] = cvt_tf32(Bs[n0 * 132 + k0]);
                bf[nt][1] = cvt_tf32(Bs[n0 * 132 + k0 + 4]);
            }
#pragma unroll
            for (int mt = 0; mt < 2; mt++)
#pragma unroll
                for (int nt = 0; nt < 4; nt++) mma8(c[mt][nt], af[mt], bf[nt]);
        }
        const int d0 = ch * 128;
#pragma unroll
        for (int mt = 0; mt < 2; mt++)
#pragma unroll
            for (int h = 0; h < 2; h++) {
                if (!vv[mt][h]) continue;
                float* op = out + (size_t)tk[mt][h] * D_DIM + d0 + wn * 32 + lk * 2;
                if (slot == 0) {
#pragma unroll
                    for (int nt = 0; nt < 4; nt++)
                        *(float2*)(op + nt * 8) =
                            make_float2(c[mt][nt][h * 2], c[mt][nt][h * 2 + 1]);
                } else {
#pragma unroll
                    for (int nt = 0; nt < 4; nt++) {
                        float2 o = *(const float2*)(op + nt * 8);
                        o.x += c[mt][nt][h * 2];
                        o.y += c[mt][nt][h * 2 + 1];
                        *(float2*)(op + nt * 8) = o;
                    }
                }
            }
        __syncthreads();
    }
}

extern "C" void kernel_launch(void* const* d_in, const int* in_sizes, int n_in,
                              void* d_out, int out_size)
{
    (void)in_sizes; (void)n_in; (void)out_size;
    const float* x  = (const float*)d_in[0];
    const float* Wr = (const float*)d_in[1];
    const float* br = (const float*)d_in[2];
    const float* A  = (const float*)d_in[3];
    const float* B  = (const float*)d_in[4];
    float* out = (float*)d_out;

    cudaFuncSetAttribute(expert_kernel, cudaFuncAttributeMaxDynamicSharedMemorySize, SMEM_BYTES);
    reset_kernel<<<1, 32>>>();
    router_kernel<<<N_TOK / 4, 256>>>(x, Wr, br);
    dim3 grid(N_TOK / MT, E_NUM);
    expert_kernel<<<grid, 256, SMEM_BYTES>>>(x, A, B, out, 0);
    expert_kernel<<<grid, 256, SMEM_BYTES>>>(x, A, B, out, 1);
}